// round 10
// baseline (speedup 1.0000x reference)
#include <cuda_runtime.h>
#include <cuda_fp16.h>
#include <cstdint>

// Problem constants
#define BH      64
#define SEQ     2048
#define HD      64
#define BM      128
#define BK      128
#define NT      (SEQ/BK)
#define NTHREADS 512

#define KVELEMS ((size_t)BH * SEQ * HD)

// smem layout (byte offsets) — 128B-row swizzled tiles
#define SB_Q    0
#define SB_K0   16384
#define SB_K1   32768
#define SB_V0   49152
#define SB_V1   65536
#define SB_RED  81920                  // O-reduction buffer: 128 x 68 fp32 = 34816 B
#define SB_RSUM 116736                 // rowsum scratch: 4 x 128 fp32 = 2048 B
#define SMEM_BYTES 118784

// fp16 copies of K and V — static scratch, no allocs
__device__ __half g_Kh[KVELEMS];
__device__ __half g_Vh[KVELEMS];

__device__ __forceinline__ float ex2(float x) {
    float y;
    asm("ex2.approx.f32 %0, %1;" : "=f"(y) : "f"(x));
    return y;
}

__device__ __forceinline__ uint32_t h2u(__half2 h) { return *(uint32_t*)&h; }

__device__ __forceinline__ void ldsm4(uint32_t* r, uint32_t addr) {
    asm volatile("ldmatrix.sync.aligned.m8n8.x4.shared.b16 {%0,%1,%2,%3}, [%4];"
        : "=r"(r[0]), "=r"(r[1]), "=r"(r[2]), "=r"(r[3]) : "r"(addr));
}
__device__ __forceinline__ void ldsm4t(uint32_t* r, uint32_t addr) {
    asm volatile("ldmatrix.sync.aligned.m8n8.x4.trans.shared.b16 {%0,%1,%2,%3}, [%4];"
        : "=r"(r[0]), "=r"(r[1]), "=r"(r[2]), "=r"(r[3]) : "r"(addr));
}

__device__ __forceinline__ void mma16816(float* c, const uint32_t* a, uint32_t b0, uint32_t b1) {
    asm volatile(
        "mma.sync.aligned.m16n8k16.row.col.f32.f16.f16.f32 "
        "{%0,%1,%2,%3}, {%4,%5,%6,%7}, {%8,%9}, {%0,%1,%2,%3};"
        : "+f"(c[0]), "+f"(c[1]), "+f"(c[2]), "+f"(c[3])
        : "r"(a[0]), "r"(a[1]), "r"(a[2]), "r"(a[3]), "r"(b0), "r"(b1));
}

__device__ __forceinline__ void cpa16(uint32_t dst, const void* src) {
    asm volatile("cp.async.cg.shared.global [%0], [%1], 16;" :: "r"(dst), "l"(src) : "memory");
}
__device__ __forceinline__ void cpa_commit() { asm volatile("cp.async.commit_group;" ::: "memory"); }
__device__ __forceinline__ void cpa_wait0()  { asm volatile("cp.async.wait_group 0;" ::: "memory"); }

// copy one 128x64 fp16 tile into a swizzled 128B-row smem region
__device__ __forceinline__ void copy_tile(uint32_t dstb, const __half* src, int tid) {
    #pragma unroll
    for (int j = 0; j < 2; j++) {
        int c = tid + j * NTHREADS;          // 1024 16B chunks
        int r = c >> 3, ch = c & 7;
        cpa16(dstb + (uint32_t)(r * 128 + ((ch ^ (r & 7)) << 4)), src + r * HD + ch * 8);
    }
}

// ---- prep: convert K,V to fp16 once ----
__global__ __launch_bounds__(256)
void prep_kernel(const float* __restrict__ k, const float* __restrict__ v)
{
    size_t i = (size_t)blockIdx.x * blockDim.x + threadIdx.x;
    if (i >= KVELEMS / 8) return;
    const float4* k4 = (const float4*)k;
    const float4* v4 = (const float4*)v;
    float4 a0 = k4[2*i], a1 = k4[2*i+1];
    float4 b0 = v4[2*i], b1 = v4[2*i+1];
    uint4 kk, vv;
    kk.x = h2u(__floats2half2_rn(a0.x, a0.y)); kk.y = h2u(__floats2half2_rn(a0.z, a0.w));
    kk.z = h2u(__floats2half2_rn(a1.x, a1.y)); kk.w = h2u(__floats2half2_rn(a1.z, a1.w));
    vv.x = h2u(__floats2half2_rn(b0.x, b0.y)); vv.y = h2u(__floats2half2_rn(b0.z, b0.w));
    vv.z = h2u(__floats2half2_rn(b1.x, b1.y)); vv.w = h2u(__floats2half2_rn(b1.z, b1.w));
    ((uint4*)g_Kh)[i] = kk;
    ((uint4*)g_Vh)[i] = vv;
}

__global__ __launch_bounds__(NTHREADS, 1)
void attn_kernel(const float* __restrict__ q, float* __restrict__ out,
                 float* __restrict__ attn)
{
    extern __shared__ __half smemh[];
    const uint32_t sb  = (uint32_t)__cvta_generic_to_shared(smemh);
    const uint32_t sbQ  = sb + SB_Q;
    const uint32_t sbK0 = sb + SB_K0;
    const uint32_t sbK1 = sb + SB_K1;
    const uint32_t sbV0 = sb + SB_V0;
    const uint32_t sbV1 = sb + SB_V1;

    const int tid  = threadIdx.x;
    const int lane = tid & 31;
    const int w    = tid >> 5;
    const int g    = lane >> 2;
    const int t    = lane & 3;
    const int wm   = w & 3;     // O/S rows wm*32..+31
    const int wn   = w >> 2;    // S cols wn*32..+31  (also this warp's PV k-slice)
    const int bh   = blockIdx.y;
    const int qt   = blockIdx.x;

    const size_t qoff = ((size_t)bh * SEQ + (size_t)qt * BM) * HD;
    const float* qp  = q + qoff;
    const __half* kp = g_Kh + (size_t)bh * SEQ * HD;
    const __half* vp = g_Vh + (size_t)bh * SEQ * HD;

    // ldmatrix per-lane constants (swizzled 128B rows)
    const int aro = (lane & 7) + 8 * ((lane >> 3) & 1);   // A-frag row (Q)
    const int ahi = lane >> 4;
    const int bro = (lane & 7) + 8 * ((lane >> 4) & 1);   // K B-frag row
    const int bhi = (lane >> 3) & 1;
    const int vro = (lane & 7) + 8 * ((lane >> 3) & 1);   // V B-frag row (trans)

    const uint32_t q_rb = (uint32_t)((wm * 32 + aro) * 128);
    const int      q_sw = aro & 7;
    const uint32_t k_rb = (uint32_t)((wn * 32 + bro) * 128);
    const int      k_sw = bro & 7;

    const float QSCALE = 0.125f * 1.44269504088896f;   // (1/temp) * log2(e)

    // ---- prologue: start K(0) copy, stage Q (scaled -> fp16, swizzled) ----
    copy_tile(sbK0, kp, tid);
    cpa_commit();

    #pragma unroll
    for (int i = tid; i < BM * 16; i += NTHREADS) {      // 16 x float4 per row
        int r = i >> 4, c4 = i & 15;
        float4 val = *(const float4*)(qp + r * HD + c4 * 4);
        uint2 pk = make_uint2(h2u(__floats2half2_rn(val.x * QSCALE, val.y * QSCALE)),
                              h2u(__floats2half2_rn(val.z * QSCALE, val.w * QSCALE)));
        uint32_t byte = (uint32_t)(r * 128 + (((c4 >> 1) ^ (r & 7)) << 4) + (c4 & 1) * 8);
        *(uint2*)((char*)smemh + SB_Q + byte) = pk;
    }
    __syncthreads();

    // ---- Phase A: partial row sums of 2^(scores) over this warp's 32 cols ----
    float rs[2][2] = {{0.f, 0.f}, {0.f, 0.f}};
    #pragma unroll 1
    for (int kt = 0; kt < NT; kt++) {
        cpa_wait0();
        __syncthreads();
        if (kt + 1 < NT) {
            copy_tile((kt & 1) ? sbK0 : sbK1, kp + (size_t)(kt + 1) * BK * HD, tid);
            cpa_commit();
        }
        const uint32_t kbase = ((kt & 1) ? sbK1 : sbK0) + k_rb;
        float sa[2][2][2][4] = {};
        #pragma unroll
        for (int ks = 0; ks < 4; ks++) {
            uint32_t qa0[4], qa1[4];
            uint32_t qch = (uint32_t)(((2 * ks + ahi) ^ q_sw) << 4);
            ldsm4(qa0, sbQ + q_rb + qch);
            ldsm4(qa1, sbQ + q_rb + 2048 + qch);
            uint32_t kch = (uint32_t)(((2 * ks + bhi) ^ k_sw) << 4);
            #pragma unroll
            for (int nbq = 0; nbq < 2; nbq++) {
                uint32_t b[4];
                ldsm4(b, kbase + (uint32_t)(nbq * 2048) + kch);
                mma16816(sa[nbq][0][0], qa0, b[0], b[1]);
                mma16816(sa[nbq][0][1], qa0, b[2], b[3]);
                mma16816(sa[nbq][1][0], qa1, b[0], b[1]);
                mma16816(sa[nbq][1][1], qa1, b[2], b[3]);
            }
        }
        #pragma unroll
        for (int nbq = 0; nbq < 2; nbq++)
            #pragma unroll
            for (int mb = 0; mb < 2; mb++)
                #pragma unroll
                for (int nb = 0; nb < 2; nb++) {
                    rs[mb][0] += ex2(sa[nbq][mb][nb][0]) + ex2(sa[nbq][mb][nb][1]);
                    rs[mb][1] += ex2(sa[nbq][mb][nb][2]) + ex2(sa[nbq][mb][nb][3]);
                }
    }

    // cross-warp rowsum combine (4 n-warps)
    float* rsum = (float*)((char*)smemh + SB_RSUM);   // [4][128]
    __syncthreads();
    #pragma unroll
    for (int mb = 0; mb < 2; mb++)
        #pragma unroll
        for (int rg = 0; rg < 2; rg++) {
            float vsum = rs[mb][rg];
            vsum += __shfl_xor_sync(0xffffffffu, vsum, 1);
            vsum += __shfl_xor_sync(0xffffffffu, vsum, 2);
            if (t == 0) rsum[wn * 128 + wm * 32 + mb * 16 + rg * 8 + g] = vsum;
        }
    __syncthreads();
    float inv[2][2];
    #pragma unroll
    for (int mb = 0; mb < 2; mb++)
        #pragma unroll
        for (int rg = 0; rg < 2; rg++) {
            int r = wm * 32 + mb * 16 + rg * 8 + g;
            inv[mb][rg] = 1.0f / (rsum[r] + rsum[128 + r] + rsum[256 + r] + rsum[384 + r]);
        }
    __syncthreads();

    // ---- Phase B: recompute S, write attn, P stays in registers, O += P @ V ----
    float oc[2][8][4] = {};   // partial O: 32 rows x 64 cols, k-sum over this warp's slices
    float* attn_base = attn + ((size_t)bh * SEQ + (size_t)qt * BM) * SEQ;

    copy_tile(sbK0, kp, tid);
    copy_tile(sbV0, vp, tid);
    cpa_commit();

    #pragma unroll 1
    for (int kt = 0; kt < NT; kt++) {
        cpa_wait0();
        __syncthreads();
        if (kt + 1 < NT) {
            copy_tile((kt & 1) ? sbK0 : sbK1, kp + (size_t)(kt + 1) * BK * HD, tid);
            copy_tile((kt & 1) ? sbV0 : sbV1, vp + (size_t)(kt + 1) * BK * HD, tid);
            cpa_commit();
        }
        const uint32_t kbase = ((kt & 1) ? sbK1 : sbK0) + k_rb;
        const uint32_t vbase = (kt & 1) ? sbV1 : sbV0;
        float* ap = attn_base + kt * BK;

        float sa[2][2][2][4] = {};
        #pragma unroll
        for (int ks = 0; ks < 4; ks++) {
            uint32_t qa0[4], qa1[4];
            uint32_t qch = (uint32_t)(((2 * ks + ahi) ^ q_sw) << 4);
            ldsm4(qa0, sbQ + q_rb + qch);
            ldsm4(qa1, sbQ + q_rb + 2048 + qch);
            uint32_t kch = (uint32_t)(((2 * ks + bhi) ^ k_sw) << 4);
            #pragma unroll
            for (int nbq = 0; nbq < 2; nbq++) {
                uint32_t b[4];
                ldsm4(b, kbase + (uint32_t)(nbq * 2048) + kch);
                mma16816(sa[nbq][0][0], qa0, b[0], b[1]);
                mma16816(sa[nbq][0][1], qa0, b[2], b[3]);
                mma16816(sa[nbq][1][0], qa1, b[0], b[1]);
                mma16816(sa[nbq][1][1], qa1, b[2], b[3]);
            }
        }

        #pragma unroll
        for (int nbq = 0; nbq < 2; nbq++) {
            // softmax + attn store + pack P A-fragments (k-chunk = this warp's 16 cols)
            uint32_t pa0[4], pa1[4];
            #pragma unroll
            for (int mb = 0; mb < 2; mb++) {
                uint32_t* pa = mb ? pa1 : pa0;
                #pragma unroll
                for (int nb = 0; nb < 2; nb++) {
                    float p0 = ex2(sa[nbq][mb][nb][0]) * inv[mb][0];
                    float p1 = ex2(sa[nbq][mb][nb][1]) * inv[mb][0];
                    float p2 = ex2(sa[nbq][mb][nb][2]) * inv[mb][1];
                    float p3 = ex2(sa[nbq][mb][nb][3]) * inv[mb][1];
                    const int col = wn * 32 + nbq * 16 + nb * 8 + 2 * t;
                    const int row = wm * 32 + mb * 16 + g;
                    *(float2*)(ap + (size_t)row       * SEQ + col) = make_float2(p0, p1);
                    *(float2*)(ap + (size_t)(row + 8) * SEQ + col) = make_float2(p2, p3);
                    pa[nb * 2]     = h2u(__floats2half2_rn(p0, p1));
                    pa[nb * 2 + 1] = h2u(__floats2half2_rn(p2, p3));
                }
            }
            // O += P(chunk) @ V(rows = this warp's k-slice)
            const uint32_t vrow_b = (uint32_t)((wn * 32 + nbq * 16 + vro) * 128);
            #pragma unroll
            for (int nb2 = 0; nb2 < 4; nb2++) {
                uint32_t vb[4];
                uint32_t ch = (uint32_t)((((nb2 * 2 + (lane >> 4)) ^ (lane & 7))) << 4);
                ldsm4t(vb, vbase + vrow_b + ch);
                mma16816(oc[0][2 * nb2],     pa0, vb[0], vb[1]);
                mma16816(oc[0][2 * nb2 + 1], pa0, vb[2], vb[3]);
                mma16816(oc[1][2 * nb2],     pa1, vb[0], vb[1]);
                mma16816(oc[1][2 * nb2 + 1], pa1, vb[2], vb[3]);
            }
        }
    }

    // ---- cross-warp O reduction (4 n-warp partials) + store ----
    float* red = (float*)((char*)smemh + SB_RED);   // [128][68]
    __syncthreads();
    #pragma unroll 1
    for (int r = 0; r < 4; r++) {
        if (wn == r) {
            #pragma unroll
            for (int mb = 0; mb < 2; mb++)
                #pragma unroll
                for (int nbo = 0; nbo < 8; nbo++) {
                    const int row = wm * 32 + mb * 16 + g;
                    const int col = nbo * 8 + 2 * t;
                    float* d0 = red + row * 68 + col;
                    float* d1 = red + (row + 8) * 68 + col;
                    if (r == 0) {
                        d0[0] = oc[mb][nbo][0]; d0[1] = oc[mb][nbo][1];
                        d1[0] = oc[mb][nbo][2]; d1[1] = oc[mb][nbo][3];
                    } else {
                        d0[0] += oc[mb][nbo][0]; d0[1] += oc[mb][nbo][1];
                        d1[0] += oc[mb][nbo][2]; d1[1] += oc[mb][nbo][3];
                    }
                }
        }
        __syncthreads();
    }
    float* op = out + qoff;
    #pragma unroll
    for (int i = tid; i < BM * (HD / 4); i += NTHREADS) {
        int row = i >> 4, c4 = (i & 15) * 4;
        *(float4*)(op + row * HD + c4) = *(float4*)(red + row * 68 + c4);
    }
}

extern "C" void kernel_launch(void* const* d_in, const int* in_sizes, int n_in,
                              void* d_out, int out_size)
{
    const float* q = (const float*)d_in[0];
    const float* k = (const float*)d_in[1];
    const float* v = (const float*)d_in[2];
    float* out  = (float*)d_out;
    float* attn = out + (size_t)BH * SEQ * HD;   // output first, then attn

    cudaFuncSetAttribute(attn_kernel, cudaFuncAttributeMaxDynamicSharedMemorySize, SMEM_BYTES);

    prep_kernel<<<(unsigned)((KVELEMS / 8 + 255) / 256), 256>>>(k, v);

    dim3 grid(SEQ / BM, BH);
    attn_kernel<<<grid, NTHREADS, SMEM_BYTES>>>(q, out, attn);
}

// round 11
// speedup vs baseline: 1.4276x; 1.4276x over previous
#include <cuda_runtime.h>
#include <cuda_fp16.h>
#include <cstdint>

// Problem constants
#define BH      64
#define SEQ     2048
#define HD      64
#define BM      128
#define BK      128
#define NT      (SEQ/BK)
#define KSH     72      // K/V smem row stride (halfs) = 144B : ldsm-clean per 8-row phase
#define PSH     136     // P smem row stride (halfs) = 272B : ldsm-clean per 8-row phase
#define NTHREADS 512

#define KVELEMS ((size_t)BH * SEQ * HD)

// smem layout (half offsets)
#define OFF_K0  0
#define OFF_K1  (BK*KSH)            // 9216
#define OFF_V0  (2*BK*KSH)          // 18432
#define OFF_V1  (3*BK*KSH)          // 27648
#define OFF_PS  (4*BK*KSH)          // 36864
#define SMEM_HALFS (OFF_PS + BM*PSH)  // 54272
#define SMEM_BYTES (SMEM_HALFS * 2)   // 108544

#define KSTEP_B (16*KSH*2)          // byte stride between 16-row K blocks

// fp16 copies of K and V (16 MB each) — static scratch, no allocs
__device__ __half g_Kh[KVELEMS];
__device__ __half g_Vh[KVELEMS];

__device__ __forceinline__ float ex2(float x) {
    float y;
    asm("ex2.approx.f32 %0, %1;" : "=f"(y) : "f"(x));
    return y;
}

__device__ __forceinline__ uint32_t h2u(__half2 h) { return *(uint32_t*)&h; }

__device__ __forceinline__ void ldsm4(uint32_t* r, uint32_t addr) {
    asm volatile("ldmatrix.sync.aligned.m8n8.x4.shared.b16 {%0,%1,%2,%3}, [%4];"
        : "=r"(r[0]), "=r"(r[1]), "=r"(r[2]), "=r"(r[3]) : "r"(addr));
}
__device__ __forceinline__ void ldsm4t(uint32_t* r, uint32_t addr) {
    asm volatile("ldmatrix.sync.aligned.m8n8.x4.trans.shared.b16 {%0,%1,%2,%3}, [%4];"
        : "=r"(r[0]), "=r"(r[1]), "=r"(r[2]), "=r"(r[3]) : "r"(addr));
}

__device__ __forceinline__ void mma16816(float* c, const uint32_t* a, uint32_t b0, uint32_t b1) {
    asm volatile(
        "mma.sync.aligned.m16n8k16.row.col.f32.f16.f16.f32 "
        "{%0,%1,%2,%3}, {%4,%5,%6,%7}, {%8,%9}, {%0,%1,%2,%3};"
        : "+f"(c[0]), "+f"(c[1]), "+f"(c[2]), "+f"(c[3])
        : "r"(a[0]), "r"(a[1]), "r"(a[2]), "r"(a[3]), "r"(b0), "r"(b1));
}

__device__ __forceinline__ void cpa16(uint32_t dst, const void* src) {
    asm volatile("cp.async.ca.shared.global [%0], [%1], 16;" :: "r"(dst), "l"(src) : "memory");
}
__device__ __forceinline__ void cpa_commit() { asm volatile("cp.async.commit_group;" ::: "memory"); }
__device__ __forceinline__ void cpa_wait0()  { asm volatile("cp.async.wait_group 0;" ::: "memory"); }

// copy one 128x64 fp16 tile into smem (row stride KSH halfs)
__device__ __forceinline__ void copy_tile(uint32_t sb, int off_halfs, const __half* src, int tid) {
    uint32_t dst0 = sb + (uint32_t)off_halfs * 2;
    #pragma unroll
    for (int j = 0; j < 2; j++) {
        int c   = tid + j * NTHREADS;   // 0..1023 16B-chunks, 8 per row
        int r   = c >> 3;
        int c16 = (c & 7) * 8;          // half offset
        cpa16(dst0 + (uint32_t)(r * KSH + c16) * 2, src + r * HD + c16);
    }
}

// ---- prep: convert K,V to fp16 once ----
__global__ __launch_bounds__(256)
void prep_kernel(const float* __restrict__ k, const float* __restrict__ v)
{
    size_t i = (size_t)blockIdx.x * blockDim.x + threadIdx.x;   // 8-float chunk
    if (i >= KVELEMS / 8) return;
    const float4* k4 = (const float4*)k;
    const float4* v4 = (const float4*)v;
    float4 a0 = k4[2*i], a1 = k4[2*i+1];
    float4 b0 = v4[2*i], b1 = v4[2*i+1];
    uint4 kk, vv;
    kk.x = h2u(__floats2half2_rn(a0.x, a0.y)); kk.y = h2u(__floats2half2_rn(a0.z, a0.w));
    kk.z = h2u(__floats2half2_rn(a1.x, a1.y)); kk.w = h2u(__floats2half2_rn(a1.z, a1.w));
    vv.x = h2u(__floats2half2_rn(b0.x, b0.y)); vv.y = h2u(__floats2half2_rn(b0.z, b0.w));
    vv.z = h2u(__floats2half2_rn(b1.x, b1.y)); vv.w = h2u(__floats2half2_rn(b1.z, b1.w));
    ((uint4*)g_Kh)[i] = kk;
    ((uint4*)g_Vh)[i] = vv;
}

__global__ __launch_bounds__(NTHREADS, 1)
void attn_kernel(const float* __restrict__ q, float* __restrict__ out,
                 float* __restrict__ attn)
{
    extern __shared__ __half smemh[];
    const uint32_t sb = (uint32_t)__cvta_generic_to_shared(smemh);

    const int tid  = threadIdx.x;
    const int lane = tid & 31;
    const int w    = tid >> 5;
    const int g    = lane >> 2;
    const int t    = lane & 3;
    const int wm   = w & 3;     // rows wm*32..+31
    const int wn   = w >> 2;    // S-cols wn*32..+31 ; O-cols wn*16..+15
    const int bh   = blockIdx.y;
    const int qt   = blockIdx.x;

    const size_t qoff = ((size_t)bh * SEQ + (size_t)qt * BM) * HD;
    const float* qp  = q + qoff;
    const __half* kp = g_Kh + (size_t)bh * SEQ * HD;
    const __half* vp = g_Vh + (size_t)bh * SEQ * HD;

    // ldmatrix lane addresses (byte offsets relative to region bases)
    const int a_row = (lane & 7) + 8 * ((lane >> 3) & 1);         // A frags (Q, P)
    const uint32_t qrel = (uint32_t)((wm * 32 + a_row) * KSH) * 2 + (lane >> 4) * 16;
    const uint32_t prel = (uint32_t)((wm * 32 + a_row) * PSH) * 2 + (lane >> 4) * 16;
    const int b_row = (lane & 7) + 8 * ((lane >> 4) & 1);         // QK B frags (K rows = n)
    const uint32_t brel = (uint32_t)((wn * 32 + b_row) * KSH) * 2 + ((lane >> 3) & 1) * 16;
    const int v_row = (lane & 7) + 8 * ((lane >> 3) & 1);         // PV B frags (V rows = k, trans)
    const uint32_t vrel = (uint32_t)(v_row * KSH) * 2 + wn * 32 + (lane >> 4) * 16;

    const float QSCALE = 0.125f * 1.44269504088896f;   // (1/temp) * log2(e)

    // ---- Stage Q (scaled -> fp16) into K0 region, keep A-fragments resident ----
    #pragma unroll
    for (int i = tid; i < BM * (HD / 4); i += NTHREADS) {
        int r = i >> 4, c = (i & 15) * 4;
        float4 val = *(const float4*)(qp + r * HD + c);
        uint2 pk = make_uint2(h2u(__floats2half2_rn(val.x * QSCALE, val.y * QSCALE)),
                              h2u(__floats2half2_rn(val.z * QSCALE, val.w * QSCALE)));
        *(uint2*)&smemh[OFF_K0 + r * KSH + c] = pk;
    }
    __syncthreads();

    uint32_t qa[2][4][4];    // [mb][k16-step][frag]
    #pragma unroll
    for (int mb = 0; mb < 2; mb++)
        #pragma unroll
        for (int ks = 0; ks < 4; ks++)
            ldsm4(qa[mb][ks], sb + qrel + (uint32_t)(mb * 16 * KSH * 2) + ks * 32);
    __syncthreads();

    // ---- Phase A: partial row sums of 2^(scores) ----
    copy_tile(sb, OFF_K0, kp, tid);
    cpa_commit();

    float rs[2][2] = {{0.f, 0.f}, {0.f, 0.f}};
    #pragma unroll 1
    for (int kt = 0; kt < NT; kt++) {
        cpa_wait0();
        __syncthreads();
        if (kt + 1 < NT) {
            copy_tile(sb, (kt & 1) ? OFF_K0 : OFF_K1, kp + (size_t)(kt + 1) * BK * HD, tid);
            cpa_commit();
        }
        uint32_t bK = sb + (uint32_t)((kt & 1) ? OFF_K1 : OFF_K0) * 2 + brel;

        uint32_t b[2][4];
        ldsm4(b[0], bK);   // (nbq=0, ks=0)
        #pragma unroll
        for (int nbq = 0; nbq < 2; nbq++) {
            float sa[2][2][4] = {};
            #pragma unroll
            for (int ks = 0; ks < 4; ks++) {
                const int i = nbq * 4 + ks;
                if (i < 7) {
                    const int j = i + 1;
                    ldsm4(b[j & 1], bK + (uint32_t)((j >> 2) * KSTEP_B) + (uint32_t)((j & 3) * 32));
                }
                const uint32_t* bc = b[i & 1];
                mma16816(sa[0][0], qa[0][ks], bc[0], bc[1]);
                mma16816(sa[0][1], qa[0][ks], bc[2], bc[3]);
                mma16816(sa[1][0], qa[1][ks], bc[0], bc[1]);
                mma16816(sa[1][1], qa[1][ks], bc[2], bc[3]);
            }
            #pragma unroll
            for (int mb = 0; mb < 2; mb++)
                #pragma unroll
                for (int nb = 0; nb < 2; nb++) {
                    rs[mb][0] += ex2(sa[mb][nb][0]) + ex2(sa[mb][nb][1]);
                    rs[mb][1] += ex2(sa[mb][nb][2]) + ex2(sa[mb][nb][3]);
                }
        }
        __syncthreads();
    }

    // cross-warp rowsum combine (4 n-warps) via smem scratch in Ps region
    float* rsum = (float*)(smemh + OFF_PS);   // [4][128] floats
    #pragma unroll
    for (int mb = 0; mb < 2; mb++)
        #pragma unroll
        for (int rg = 0; rg < 2; rg++) {
            float vsum = rs[mb][rg];
            vsum += __shfl_xor_sync(0xffffffffu, vsum, 1);
            vsum += __shfl_xor_sync(0xffffffffu, vsum, 2);
            if (t == 0) rsum[wn * 128 + wm * 32 + mb * 16 + rg * 8 + g] = vsum;
        }
    __syncthreads();
    float inv[2][2];
    #pragma unroll
    for (int mb = 0; mb < 2; mb++)
        #pragma unroll
        for (int rg = 0; rg < 2; rg++) {
            int r = wm * 32 + mb * 16 + rg * 8 + g;
            inv[mb][rg] = 1.0f / (rsum[r] + rsum[128 + r] + rsum[256 + r] + rsum[384 + r]);
        }
    __syncthreads();

    // ---- Phase B ----
    float oc[2][2][4] = {};

    float* attn_base = attn + ((size_t)bh * SEQ + (size_t)qt * BM) * SEQ;

    copy_tile(sb, OFF_K0, kp, tid);
    copy_tile(sb, OFF_V0, vp, tid);
    cpa_commit();

    #pragma unroll 1
    for (int kt = 0; kt < NT; kt++) {
        cpa_wait0();
        __syncthreads();
        if (kt + 1 < NT) {
            copy_tile(sb, (kt & 1) ? OFF_K0 : OFF_K1, kp + (size_t)(kt + 1) * BK * HD, tid);
            copy_tile(sb, (kt & 1) ? OFF_V0 : OFF_V1, vp + (size_t)(kt + 1) * BK * HD, tid);
            cpa_commit();
        }
        uint32_t bK = sb + (uint32_t)((kt & 1) ? OFF_K1 : OFF_K0) * 2 + brel;
        uint32_t bV = sb + (uint32_t)((kt & 1) ? OFF_V1 : OFF_V0) * 2 + vrel;
        float* ap = attn_base + kt * BK;

        uint32_t b[2][4];
        ldsm4(b[0], bK);
        #pragma unroll
        for (int nbq = 0; nbq < 2; nbq++) {
            float sa[2][2][4] = {};
            #pragma unroll
            for (int ks = 0; ks < 4; ks++) {
                const int i = nbq * 4 + ks;
                if (i < 7) {
                    const int j = i + 1;
                    ldsm4(b[j & 1], bK + (uint32_t)((j >> 2) * KSTEP_B) + (uint32_t)((j & 3) * 32));
                }
                const uint32_t* bc = b[i & 1];
                mma16816(sa[0][0], qa[0][ks], bc[0], bc[1]);
                mma16816(sa[0][1], qa[0][ks], bc[2], bc[3]);
                mma16816(sa[1][0], qa[1][ks], bc[0], bc[1]);
                mma16816(sa[1][1], qa[1][ks], bc[2], bc[3]);
            }
            #pragma unroll
            for (int mb = 0; mb < 2; mb++)
                #pragma unroll
                for (int nb = 0; nb < 2; nb++) {
                    const int col = wn * 32 + nbq * 16 + nb * 8 + 2 * t;
                    const int row = wm * 32 + mb * 16 + g;
                    float p0 = ex2(sa[mb][nb][0]) * inv[mb][0];
                    float p1 = ex2(sa[mb][nb][1]) * inv[mb][0];
                    float p2 = ex2(sa[mb][nb][2]) * inv[mb][1];
                    float p3 = ex2(sa[mb][nb][3]) * inv[mb][1];
                    *(uint32_t*)&smemh[OFF_PS + row * PSH + col]       = h2u(__floats2half2_rn(p0, p1));
                    *(uint32_t*)&smemh[OFF_PS + (row + 8) * PSH + col] = h2u(__floats2half2_rn(p2, p3));
                    *(float2*)(ap + (size_t)row       * SEQ + col) = make_float2(p0, p1);
                    *(float2*)(ap + (size_t)(row + 8) * SEQ + col) = make_float2(p2, p3);
                }
        }
        __syncthreads();   // Ps complete, K consumed

        // O += P @ V  — pipelined pa/vb fragment sets
        {
            uint32_t pa0[2][4], pa1[2][4], vb[2][4];
            ldsm4 (pa0[0], sb + (uint32_t)OFF_PS * 2 + prel);
            ldsm4 (pa1[0], sb + (uint32_t)OFF_PS * 2 + prel + (uint32_t)(16 * PSH * 2));
            ldsm4t(vb[0],  bV);
            #pragma unroll
            for (int kb = 0; kb < 8; kb++) {
                const int cur = kb & 1, nxt = cur ^ 1;
                if (kb < 7) {
                    ldsm4 (pa0[nxt], sb + (uint32_t)OFF_PS * 2 + prel + (kb + 1) * 32);
                    ldsm4 (pa1[nxt], sb + (uint32_t)OFF_PS * 2 + prel + (uint32_t)(16 * PSH * 2) + (kb + 1) * 32);
                    ldsm4t(vb[nxt],  bV + (uint32_t)((kb + 1) * 16 * KSH * 2));
                }
                mma16816(oc[0][0], pa0[cur], vb[cur][0], vb[cur][1]);
                mma16816(oc[0][1], pa0[cur], vb[cur][2], vb[cur][3]);
                mma16816(oc[1][0], pa1[cur], vb[cur][0], vb[cur][1]);
                mma16816(oc[1][1], pa1[cur], vb[cur][2], vb[cur][3]);
            }
        }
        // next loop-top barrier protects Ps/V from overwrite
    }

    // ---- write O ----
    float* op = out + qoff;
    #pragma unroll
    for (int mb = 0; mb < 2; mb++) {
        const int r00 = wm * 32 + mb * 16 + g;
        #pragma unroll
        for (int nb = 0; nb < 2; nb++) {
            const int col = wn * 16 + nb * 8 + 2 * t;
            *(float2*)(op + r00       * HD + col) = make_float2(oc[mb][nb][0], oc[mb][nb][1]);
            *(float2*)(op + (r00 + 8) * HD + col) = make_float2(oc[mb][nb][2], oc[mb][nb][3]);
        }
    }
}

extern "C" void kernel_launch(void* const* d_in, const int* in_sizes, int n_in,
                              void* d_out, int out_size)
{
    const float* q = (const float*)d_in[0];
    const float* k = (const float*)d_in[1];
    const float* v = (const float*)d_in[2];
    float* out  = (float*)d_out;
    float* attn = out + (size_t)BH * SEQ * HD;   // output first, then attn

    cudaFuncSetAttribute(attn_kernel, cudaFuncAttributeMaxDynamicSharedMemorySize, SMEM_BYTES);

    prep_kernel<<<(unsigned)((KVELEMS / 8 + 255) / 256), 256>>>(k, v);

    dim3 grid(SEQ / BM, BH);
    attn_kernel<<<grid, NTHREADS, SMEM_BYTES>>>(q, out, attn);
}